// round 2
// baseline (speedup 1.0000x reference)
#include <cuda_runtime.h>

// y[b,c,h,w] = coef[c] * g[b,c,h,w]
// g: (32, 512, 64, 64) fp32. Plane H*W = 4096 floats = 1024 float4.
// Persistent grid-stride kernel: grid = 152 SMs * 8 resident blocks = 1216.
// Each loop iteration processes one (b,c) plane (1024 float4s, 256 thr x 4).
// Streaming hints (__ldcs/__stcs): data is touched once, keep L2 clean.

#define NPLANES (32u * 512u)   // 16384 planes
#define PLANE_V4 1024u         // float4s per plane

__global__ void __launch_bounds__(256, 8) scale_kernel(
    const float4* __restrict__ g,
    const float* __restrict__ coef,
    float4* __restrict__ out)
{
    for (unsigned plane = blockIdx.x; plane < NPLANES; plane += gridDim.x) {
        const float s = __ldg(coef + (plane & 511u));   // tiny, L1-resident
        const unsigned base = plane * PLANE_V4 + threadIdx.x;

        // 4 independent front-batched streaming loads (stride 4 KiB) -> MLP=4
        float4 a0 = __ldcs(g + base);
        float4 a1 = __ldcs(g + base + 256u);
        float4 a2 = __ldcs(g + base + 512u);
        float4 a3 = __ldcs(g + base + 768u);

        a0.x *= s; a0.y *= s; a0.z *= s; a0.w *= s;
        a1.x *= s; a1.y *= s; a1.z *= s; a1.w *= s;
        a2.x *= s; a2.y *= s; a2.z *= s; a2.w *= s;
        a3.x *= s; a3.y *= s; a3.z *= s; a3.w *= s;

        __stcs(out + base,        a0);
        __stcs(out + base + 256u, a1);
        __stcs(out + base + 512u, a2);
        __stcs(out + base + 768u, a3);
    }
}

extern "C" void kernel_launch(void* const* d_in, const int* in_sizes, int n_in,
                              void* d_out, int out_size)
{
    const float4* g    = (const float4*)d_in[0];
    const float*  coef = (const float*)d_in[1];
    float4*       out  = (float4*)d_out;

    // Exact-fit persistent grid: 152 SMs x 8 resident blocks.
    scale_kernel<<<152 * 8, 256>>>(g, coef, out);
}